// round 4
// baseline (speedup 1.0000x reference)
#include <cuda_runtime.h>
#include <cstdint>
#include <cstddef>

// Problem constants
#define BQ    8
#define CIN   64
#define TLEN  1024
#define FF    256
#define COUT  64
#define GG    32
#define UU    8

// Tiling
#define TILE_T          32
#define TSPLIT          4
#define T_PER_BLOCK     (TLEN / TSPLIT)        // 256
#define TILES_PER_BLOCK (T_PER_BLOCK / TILE_T) // 8

// SMEM layout (floats)
#define WS_USTRIDE 4104                         // 64*64 + 8 pad (breaks 4-way u-bank collision)
#define WS_FLOATS  (UU * WS_USTRIDE)            // 32832
#define XS_TSTRIDE 10                           // 8 data + 2 pad floats per t
#define XS_ISTRIDE (TILE_T * XS_TSTRIDE)        // 320
#define XS_FLOATS  (CIN * XS_ISTRIDE)           // 20480
#define SMEM_BYTES ((WS_FLOATS + XS_FLOATS) * 4)  // 213248 < 227 KB max dyn smem

typedef unsigned long long ull;

// ---- packed f32x2 helpers (sm_103a) ----
__device__ __forceinline__ ull splat2(float x) {
    ull d; unsigned u = __float_as_uint(x);
    asm("mov.b64 %0, {%1, %1};" : "=l"(d) : "r"(u));
    return d;
}
__device__ __forceinline__ void fma2(ull& d, ull a, ull b) {
    asm("fma.rn.f32x2 %0, %1, %2, %0;" : "+l"(d) : "l"(a), "l"(b));
}
__device__ __forceinline__ float2 unpack2(ull v) {
    unsigned lo, hi;
    asm("mov.b64 {%0, %1}, %2;" : "=r"(lo), "=r"(hi) : "l"(v));
    return make_float2(__uint_as_float(lo), __uint_as_float(hi));
}

__global__ void __launch_bounds__(256, 1)
grouped_linear_cf_kernel(const float* __restrict__ x,
                         const float* __restrict__ w,
                         const float* __restrict__ bias,
                         float* __restrict__ y)
{
    extern __shared__ float smem[];
    float* ws = smem;               // [u][i*64+o] padded per-u
    float* xs = smem + WS_FLOATS;   // [i][t][u] padded t-stride

    const int g   = blockIdx.x;   // group 0..31
    const int b   = blockIdx.y;   // batch 0..7
    const int tz  = blockIdx.z;   // t-split 0..3
    const int tid = threadIdx.x;

    const int u_blk = tid & 3;          // 4 u-pairs
    const int t_blk = (tid >> 2) & 7;   // 8 t-quads
    const int o_blk = tid >> 5;         // warp id = o-octet (uniform per warp)
    const int u0    = 2 * u_blk;

    // ---- load this group's weights into SMEM (once per block) ----
    {
        const float4* wg = reinterpret_cast<const float4*>(w + (size_t)g * (UU * CIN * COUT));
        for (int idx = tid; idx < (UU * CIN * COUT) / 4; idx += 256) {
            float4 v = wg[idx];
            int u   = idx >> 10;     // 1024 float4 per u
            int rem = idx & 1023;    // float4 index within u: covers i*64+o
            *reinterpret_cast<float4*>(ws + u * WS_USTRIDE + rem * 4) = v;
        }
    }

    // ---- per-thread bias: {bias[f=g*8+u0], bias[f+1]} for each of 8 o's ----
    float2 bz[8];
#pragma unroll
    for (int oo = 0; oo < 8; ++oo)
        bz[oo] = *reinterpret_cast<const float2*>(
            bias + (size_t)(o_blk * 8 + oo) * FF + g * UU + u0);

    const float* xg = x + (size_t)b * CIN * TLEN * FF + (size_t)g * UU;
    float*       yg = y + (size_t)b * COUT * TLEN * FF + (size_t)g * UU + u0;

    const float* xbase  = xs + t_blk * 4 * XS_TSTRIDE + u0;
    const float* wbase0 = ws + u0 * WS_USTRIDE + o_blk * 8;
    const float* wbase1 = wbase0 + WS_USTRIDE;

    for (int tile = 0; tile < TILES_PER_BLOCK; ++tile) {
        const int t0 = tz * T_PER_BLOCK + tile * TILE_T;

        __syncthreads();  // W ready (tile 0) / previous tile's compute done

        // ---- load x tile: each (i,t) is one full 32B sector (8 f's of the group) ----
#pragma unroll
        for (int idx = tid; idx < CIN * TILE_T * 2; idx += 256) {
            int i    = idx >> 6;
            int rem  = idx & 63;
            int t    = rem >> 1;
            int half = rem & 1;
            const float4 v = *reinterpret_cast<const float4*>(
                xg + (size_t)i * (TLEN * FF) + (size_t)(t0 + t) * FF + half * 4);
            float* dst = xs + i * XS_ISTRIDE + t * XS_TSTRIDE + half * 4;
            *reinterpret_cast<float2*>(dst)     = make_float2(v.x, v.y);
            *reinterpret_cast<float2*>(dst + 2) = make_float2(v.z, v.w);
        }
        __syncthreads();

        // ---- compute: 4t x 8o x 2u per thread; FFMA2 pairs over adjacent o ----
        ull acc[2][4][4];
#pragma unroll
        for (int a = 0; a < 2; ++a)
#pragma unroll
            for (int tt = 0; tt < 4; ++tt)
#pragma unroll
                for (int op = 0; op < 4; ++op) acc[a][tt][op] = 0ull;

#pragma unroll 4
        for (int i = 0; i < CIN; ++i) {
            const float* xr = xbase + i * XS_ISTRIDE;
            float2 xv0 = *reinterpret_cast<const float2*>(xr);
            float2 xv1 = *reinterpret_cast<const float2*>(xr + XS_TSTRIDE);
            float2 xv2 = *reinterpret_cast<const float2*>(xr + 2 * XS_TSTRIDE);
            float2 xv3 = *reinterpret_cast<const float2*>(xr + 3 * XS_TSTRIDE);

            // weight o-pairs, broadcast across the warp (o_blk uniform)
            ulonglong2 w0a = *reinterpret_cast<const ulonglong2*>(wbase0 + i * COUT);
            ulonglong2 w0b = *reinterpret_cast<const ulonglong2*>(wbase0 + i * COUT + 4);
            ulonglong2 w1a = *reinterpret_cast<const ulonglong2*>(wbase1 + i * COUT);
            ulonglong2 w1b = *reinterpret_cast<const ulonglong2*>(wbase1 + i * COUT + 4);

            ull s0[4] = { splat2(xv0.x), splat2(xv1.x), splat2(xv2.x), splat2(xv3.x) };
            ull s1[4] = { splat2(xv0.y), splat2(xv1.y), splat2(xv2.y), splat2(xv3.y) };

#pragma unroll
            for (int tt = 0; tt < 4; ++tt) {
                fma2(acc[0][tt][0], s0[tt], w0a.x);
                fma2(acc[0][tt][1], s0[tt], w0a.y);
                fma2(acc[0][tt][2], s0[tt], w0b.x);
                fma2(acc[0][tt][3], s0[tt], w0b.y);
                fma2(acc[1][tt][0], s1[tt], w1a.x);
                fma2(acc[1][tt][1], s1[tt], w1a.y);
                fma2(acc[1][tt][2], s1[tt], w1b.x);
                fma2(acc[1][tt][3], s1[tt], w1b.y);
            }
        }

        // ---- epilogue: repack (u0,u1) pairs -> float2 stores over adjacent f ----
#pragma unroll
        for (int tt = 0; tt < 4; ++tt) {
            const int t = t0 + t_blk * 4 + tt;
            float* yrow = yg + (size_t)t * FF;
#pragma unroll
            for (int op = 0; op < 4; ++op) {
                float2 a0 = unpack2(acc[0][tt][op]);  // {o_even, o_odd} @ u0
                float2 a1 = unpack2(acc[1][tt][op]);  // {o_even, o_odd} @ u0+1
                int oe = o_blk * 8 + 2 * op;
                float2 r0 = make_float2(a0.x + bz[2 * op].x,     a1.x + bz[2 * op].y);
                float2 r1 = make_float2(a0.y + bz[2 * op + 1].x, a1.y + bz[2 * op + 1].y);
                *reinterpret_cast<float2*>(yrow + (size_t)oe * (TLEN * FF))       = r0;
                *reinterpret_cast<float2*>(yrow + (size_t)(oe + 1) * (TLEN * FF)) = r1;
            }
        }
    }
}

extern "C" void kernel_launch(void* const* d_in, const int* in_sizes, int n_in,
                              void* d_out, int out_size) {
    (void)in_sizes; (void)n_in; (void)out_size;
    const float* x    = (const float*)d_in[0];
    const float* w    = (const float*)d_in[1];
    const float* bias = (const float*)d_in[2];
    float*       y    = (float*)d_out;

    cudaFuncSetAttribute(grouped_linear_cf_kernel,
                         cudaFuncAttributeMaxDynamicSharedMemorySize, SMEM_BYTES);

    dim3 grid(GG, BQ, TSPLIT);   // 32 x 8 x 4 = 1024 blocks
    grouped_linear_cf_kernel<<<grid, 256, SMEM_BYTES>>>(x, w, bias, y);
}

// round 5
// speedup vs baseline: 1.0004x; 1.0004x over previous
#include <cuda_runtime.h>
#include <cstdint>
#include <cstddef>

// Problem constants
#define BQ    8
#define CIN   64
#define TLEN  1024
#define FF    256
#define COUT  64
#define GG    32
#define UU    8

// Tiling
#define TILE_T          32
#define TSPLIT          4
#define T_PER_BLOCK     (TLEN / TSPLIT)        // 256
#define TILES_PER_BLOCK (T_PER_BLOCK / TILE_T) // 8

// SMEM layout (floats)
#define WS_USTRIDE 4104                         // 64*64 + 8 pad (breaks 4-way u-bank collision)
#define WS_FLOATS  (UU * WS_USTRIDE)            // 32832
#define XS_TSTRIDE 10                           // 8 data + 2 pad floats per t
#define XS_ISTRIDE (TILE_T * XS_TSTRIDE)        // 320
#define XS_FLOATS  (CIN * XS_ISTRIDE)           // 20480
#define SMEM_BYTES ((WS_FLOATS + XS_FLOATS) * 4)  // 213248 < 227 KB max dyn smem

typedef unsigned long long ull;

// ---- packed f32x2 helpers (sm_103a) ----
__device__ __forceinline__ ull splat2(float x) {
    ull d; unsigned u = __float_as_uint(x);
    asm("mov.b64 %0, {%1, %1};" : "=l"(d) : "r"(u));
    return d;
}
__device__ __forceinline__ void fma2(ull& d, ull a, ull b) {
    asm("fma.rn.f32x2 %0, %1, %2, %0;" : "+l"(d) : "l"(a), "l"(b));
}
__device__ __forceinline__ float2 unpack2(ull v) {
    unsigned lo, hi;
    asm("mov.b64 {%0, %1}, %2;" : "=r"(lo), "=r"(hi) : "l"(v));
    return make_float2(__uint_as_float(lo), __uint_as_float(hi));
}

__global__ void __launch_bounds__(256, 1)
grouped_linear_cf_kernel(const float* __restrict__ x,
                         const float* __restrict__ w,
                         const float* __restrict__ bias,
                         float* __restrict__ y)
{
    extern __shared__ float smem[];
    float* ws = smem;               // [u][i*64+o] padded per-u
    float* xs = smem + WS_FLOATS;   // [i][t][u] padded t-stride

    const int g   = blockIdx.x;   // group 0..31
    const int b   = blockIdx.y;   // batch 0..7
    const int tz  = blockIdx.z;   // t-split 0..3
    const int tid = threadIdx.x;

    const int u_blk = tid & 3;          // 4 u-pairs
    const int t_blk = (tid >> 2) & 7;   // 8 t-quads
    const int o_blk = tid >> 5;         // warp id = o-octet (uniform per warp)
    const int u0    = 2 * u_blk;

    // ---- load this group's weights into SMEM (once per block) ----
    {
        const float4* wg = reinterpret_cast<const float4*>(w + (size_t)g * (UU * CIN * COUT));
        for (int idx = tid; idx < (UU * CIN * COUT) / 4; idx += 256) {
            float4 v = wg[idx];
            int u   = idx >> 10;     // 1024 float4 per u
            int rem = idx & 1023;    // float4 index within u: covers i*64+o
            *reinterpret_cast<float4*>(ws + u * WS_USTRIDE + rem * 4) = v;
        }
    }

    // ---- per-thread bias: {bias[f=g*8+u0], bias[f+1]} for each of 8 o's ----
    float2 bz[8];
#pragma unroll
    for (int oo = 0; oo < 8; ++oo)
        bz[oo] = *reinterpret_cast<const float2*>(
            bias + (size_t)(o_blk * 8 + oo) * FF + g * UU + u0);

    const float* xg = x + (size_t)b * CIN * TLEN * FF + (size_t)g * UU;
    float*       yg = y + (size_t)b * COUT * TLEN * FF + (size_t)g * UU + u0;

    const float* xbase  = xs + t_blk * 4 * XS_TSTRIDE + u0;
    const float* wbase0 = ws + u0 * WS_USTRIDE + o_blk * 8;
    const float* wbase1 = wbase0 + WS_USTRIDE;

    for (int tile = 0; tile < TILES_PER_BLOCK; ++tile) {
        const int t0 = tz * T_PER_BLOCK + tile * TILE_T;

        __syncthreads();  // W ready (tile 0) / previous tile's compute done

        // ---- load x tile: each (i,t) is one full 32B sector (8 f's of the group) ----
#pragma unroll
        for (int idx = tid; idx < CIN * TILE_T * 2; idx += 256) {
            int i    = idx >> 6;
            int rem  = idx & 63;
            int t    = rem >> 1;
            int half = rem & 1;
            const float4 v = *reinterpret_cast<const float4*>(
                xg + (size_t)i * (TLEN * FF) + (size_t)(t0 + t) * FF + half * 4);
            float* dst = xs + i * XS_ISTRIDE + t * XS_TSTRIDE + half * 4;
            *reinterpret_cast<float2*>(dst)     = make_float2(v.x, v.y);
            *reinterpret_cast<float2*>(dst + 2) = make_float2(v.z, v.w);
        }
        __syncthreads();

        // ---- compute: 4t x 8o x 2u per thread; FFMA2 pairs over adjacent o ----
        ull acc[2][4][4];
#pragma unroll
        for (int a = 0; a < 2; ++a)
#pragma unroll
            for (int tt = 0; tt < 4; ++tt)
#pragma unroll
                for (int op = 0; op < 4; ++op) acc[a][tt][op] = 0ull;

#pragma unroll 4
        for (int i = 0; i < CIN; ++i) {
            const float* xr = xbase + i * XS_ISTRIDE;
            float2 xv0 = *reinterpret_cast<const float2*>(xr);
            float2 xv1 = *reinterpret_cast<const float2*>(xr + XS_TSTRIDE);
            float2 xv2 = *reinterpret_cast<const float2*>(xr + 2 * XS_TSTRIDE);
            float2 xv3 = *reinterpret_cast<const float2*>(xr + 3 * XS_TSTRIDE);

            // weight o-pairs, broadcast across the warp (o_blk uniform)
            ulonglong2 w0a = *reinterpret_cast<const ulonglong2*>(wbase0 + i * COUT);
            ulonglong2 w0b = *reinterpret_cast<const ulonglong2*>(wbase0 + i * COUT + 4);
            ulonglong2 w1a = *reinterpret_cast<const ulonglong2*>(wbase1 + i * COUT);
            ulonglong2 w1b = *reinterpret_cast<const ulonglong2*>(wbase1 + i * COUT + 4);

            ull s0[4] = { splat2(xv0.x), splat2(xv1.x), splat2(xv2.x), splat2(xv3.x) };
            ull s1[4] = { splat2(xv0.y), splat2(xv1.y), splat2(xv2.y), splat2(xv3.y) };

#pragma unroll
            for (int tt = 0; tt < 4; ++tt) {
                fma2(acc[0][tt][0], s0[tt], w0a.x);
                fma2(acc[0][tt][1], s0[tt], w0a.y);
                fma2(acc[0][tt][2], s0[tt], w0b.x);
                fma2(acc[0][tt][3], s0[tt], w0b.y);
                fma2(acc[1][tt][0], s1[tt], w1a.x);
                fma2(acc[1][tt][1], s1[tt], w1a.y);
                fma2(acc[1][tt][2], s1[tt], w1b.x);
                fma2(acc[1][tt][3], s1[tt], w1b.y);
            }
        }

        // ---- epilogue: repack (u0,u1) pairs -> float2 stores over adjacent f ----
#pragma unroll
        for (int tt = 0; tt < 4; ++tt) {
            const int t = t0 + t_blk * 4 + tt;
            float* yrow = yg + (size_t)t * FF;
#pragma unroll
            for (int op = 0; op < 4; ++op) {
                float2 a0 = unpack2(acc[0][tt][op]);  // {o_even, o_odd} @ u0
                float2 a1 = unpack2(acc[1][tt][op]);  // {o_even, o_odd} @ u0+1
                int oe = o_blk * 8 + 2 * op;
                float2 r0 = make_float2(a0.x + bz[2 * op].x,     a1.x + bz[2 * op].y);
                float2 r1 = make_float2(a0.y + bz[2 * op + 1].x, a1.y + bz[2 * op + 1].y);
                *reinterpret_cast<float2*>(yrow + (size_t)oe * (TLEN * FF))       = r0;
                *reinterpret_cast<float2*>(yrow + (size_t)(oe + 1) * (TLEN * FF)) = r1;
            }
        }
    }
}

extern "C" void kernel_launch(void* const* d_in, const int* in_sizes, int n_in,
                              void* d_out, int out_size) {
    (void)in_sizes; (void)n_in; (void)out_size;
    const float* x    = (const float*)d_in[0];
    const float* w    = (const float*)d_in[1];
    const float* bias = (const float*)d_in[2];
    float*       y    = (float*)d_out;

    cudaFuncSetAttribute(grouped_linear_cf_kernel,
                         cudaFuncAttributeMaxDynamicSharedMemorySize, SMEM_BYTES);

    dim3 grid(GG, BQ, TSPLIT);   // 32 x 8 x 4 = 1024 blocks
    grouped_linear_cf_kernel<<<grid, 256, SMEM_BYTES>>>(x, w, bias, y);
}

// round 7
// speedup vs baseline: 1.0844x; 1.0841x over previous
#include <cuda_runtime.h>
#include <cstdint>
#include <cstddef>

// Problem constants
#define BQ    8
#define CIN   64
#define TLEN  1024
#define FF    256
#define COUT  64
#define GG    32
#define UU    8

// Tiling
#define O_PER_CTA 32            // o split across 2 CTAs
#define TILE_T    64
#define TILES     4             // t-tiles per CTA (covers 256 t); tz gives 4 ranges
#define ICHUNK    16
#define NCHUNK    (CIN / ICHUNK)   // 4

// SMEM layout (floats)
#define WS_UPSTRIDE 4104                  // 64i * 32o * 2(u-pair) + 8 pad -> bank offset 8 per up
#define WS_FLOATS   (4 * WS_UPSTRIDE)     // 16416
#define XS_TSTRIDE  10                    // 8 data + 2 pad
#define XS_ISTRIDE  (TILE_T * XS_TSTRIDE) // 640
#define XS_BUF      (ICHUNK * XS_ISTRIDE) // 10240
#define XS_FLOATS   (2 * XS_BUF)          // 20480 (double buffered)
#define SMEM_BYTES  ((WS_FLOATS + XS_FLOATS) * 4)   // 147584

typedef unsigned long long ull;

__device__ __forceinline__ void fma2(ull& d, ull a, ull b) {
    asm("fma.rn.f32x2 %0, %1, %2, %0;" : "+l"(d) : "l"(a), "l"(b));
}
__device__ __forceinline__ float2 unpack2(ull v) {
    unsigned lo, hi;
    asm("mov.b64 {%0, %1}, %2;" : "=r"(lo), "=r"(hi) : "l"(v));
    return make_float2(__uint_as_float(lo), __uint_as_float(hi));
}
__device__ __forceinline__ void cp_async8(uint32_t dst, const void* src) {
    asm volatile("cp.async.ca.shared.global [%0], [%1], 8;\n" :: "r"(dst), "l"(src));
}
__device__ __forceinline__ void cp_commit() {
    asm volatile("cp.async.commit_group;\n" ::: "memory");
}
template <int N>
__device__ __forceinline__ void cp_wait() {
    asm volatile("cp.async.wait_group %0;\n" :: "n"(N) : "memory");
}

__global__ void __launch_bounds__(512, 1)
grouped_linear_cf_kernel(const float* __restrict__ x,
                         const float* __restrict__ w,
                         const float* __restrict__ bias,
                         float* __restrict__ y)
{
    extern __shared__ float smem[];
    float* ws = smem;               // [up][i][o] as float2 {w[u0], w[u1]}, padded per-up
    float* xs = smem + WS_FLOATS;   // [buf][i_local][t][u] stride-10

    const int g   = blockIdx.x;          // group 0..31
    const int b   = blockIdx.y;          // batch 0..7
    const int oh  = blockIdx.z & 1;      // o-half 0..1
    const int tz  = blockIdx.z >> 1;     // t-range 0..3 (256 t each)
    const int tid = threadIdx.x;

    const int up    = tid & 3;           // u-pair 0..3, u0 = 2*up
    const int u0    = up * 2;
    const int t_lo  = (tid >> 2) & 7;
    const int warp  = tid >> 5;          // 0..15
    const int o_blk = warp & 7;          // 8 o-slots x 4 o = 32
    const int t_hi  = warp >> 3;
    const int t_blk = t_hi * 8 + t_lo;   // 0..15, 4 t each

    // ---- weights -> SMEM, u-interleaved: ws[up][i][o] = {w[2up][i][o], w[2up+1][i][o]} ----
    {
        const float* wg = w + (size_t)g * (UU * CIN * COUT) + oh * O_PER_CTA;
        for (int idx = tid; idx < 4 * CIN * O_PER_CTA * 2; idx += 512) {
            int j   = idx & 1;
            int o   = (idx >> 1) & 31;
            int i   = (idx >> 6) & 63;
            int upw = idx >> 12;
            ws[upw * WS_UPSTRIDE + i * 64 + o * 2 + j] =
                wg[((size_t)(2 * upw + j) * CIN + i) * COUT + o];
        }
    }

    // ---- per-thread bias: {bias[og][f=g*8+u0], bias[og][f+1]} ----
    float2 bz[4];
#pragma unroll
    for (int oo = 0; oo < 4; ++oo) {
        int og = oh * O_PER_CTA + o_blk * 4 + oo;
        bz[oo] = *reinterpret_cast<const float2*>(bias + (size_t)og * FF + g * UU + u0);
    }

    const float* xg = x + (size_t)b * CIN * TLEN * FF + (size_t)g * UU;
    float*       yb = y + (size_t)b * COUT * TLEN * FF;   // FIX: batch offset restored

    for (int tile = 0; tile < TILES; ++tile) {
        const int t0 = tz * (TILES * TILE_T) + tile * TILE_T;

        ull acc[4][4];
#pragma unroll
        for (int tt = 0; tt < 4; ++tt)
#pragma unroll
            for (int oo = 0; oo < 4; ++oo) acc[tt][oo] = 0ull;

        // ---- prologue: issue chunk 0 into buf 0 ----
        {
            float* dstb = xs;
#pragma unroll
            for (int k = 0; k < 8; ++k) {
                int idx = tid + k * 512;        // 4096 total: 16i x 64t x 4seg
                int il  = idx >> 8;
                int rem = idx & 255;
                int t   = rem >> 2;
                int seg = rem & 3;
                const float* src = xg + (size_t)il * (TLEN * FF)
                                      + (size_t)(t0 + t) * FF + seg * 2;
                uint32_t dst = (uint32_t)__cvta_generic_to_shared(
                    dstb + il * XS_ISTRIDE + t * XS_TSTRIDE + seg * 2);
                cp_async8(dst, src);
            }
            cp_commit();
        }

        for (int ic = 0; ic < NCHUNK; ++ic) {
            // issue next chunk into the other buffer
            if (ic + 1 < NCHUNK) {
                float* dstb = xs + ((ic + 1) & 1) * XS_BUF;
                const int ibase = (ic + 1) * ICHUNK;
#pragma unroll
                for (int k = 0; k < 8; ++k) {
                    int idx = tid + k * 512;
                    int il  = idx >> 8;
                    int rem = idx & 255;
                    int t   = rem >> 2;
                    int seg = rem & 3;
                    const float* src = xg + (size_t)(ibase + il) * (TLEN * FF)
                                          + (size_t)(t0 + t) * FF + seg * 2;
                    uint32_t dst = (uint32_t)__cvta_generic_to_shared(
                        dstb + il * XS_ISTRIDE + t * XS_TSTRIDE + seg * 2);
                    cp_async8(dst, src);
                }
                cp_commit();
                cp_wait<1>();     // current chunk's group complete; next stays in flight
            } else {
                cp_wait<0>();
            }
            __syncthreads();

            const float* xb = xs + (ic & 1) * XS_BUF + t_blk * 4 * XS_TSTRIDE + u0;
            const float* wb = ws + up * WS_UPSTRIDE + o_blk * 8 + ic * ICHUNK * 64;

#pragma unroll 4
            for (int il = 0; il < ICHUNK; ++il) {
                const float* xr = xb + il * XS_ISTRIDE;
                // packed x pairs {x[u0], x[u1]} for 4 t — used directly as FMA2 operands
                ull xv0 = *reinterpret_cast<const ull*>(xr);
                ull xv1 = *reinterpret_cast<const ull*>(xr + XS_TSTRIDE);
                ull xv2 = *reinterpret_cast<const ull*>(xr + 2 * XS_TSTRIDE);
                ull xv3 = *reinterpret_cast<const ull*>(xr + 3 * XS_TSTRIDE);

                // weight u-pairs for 4 o's (2 x LDS.128, warp-broadcast over t_lo)
                const float* wr = wb + il * 64;
                ulonglong2 wA = *reinterpret_cast<const ulonglong2*>(wr);      // o0,o1
                ulonglong2 wB = *reinterpret_cast<const ulonglong2*>(wr + 4);  // o2,o3

                fma2(acc[0][0], xv0, wA.x); fma2(acc[0][1], xv0, wA.y);
                fma2(acc[0][2], xv0, wB.x); fma2(acc[0][3], xv0, wB.y);
                fma2(acc[1][0], xv1, wA.x); fma2(acc[1][1], xv1, wA.y);
                fma2(acc[1][2], xv1, wB.x); fma2(acc[1][3], xv1, wB.y);
                fma2(acc[2][0], xv2, wA.x); fma2(acc[2][1], xv2, wA.y);
                fma2(acc[2][2], xv2, wB.x); fma2(acc[2][3], xv2, wB.y);
                fma2(acc[3][0], xv3, wA.x); fma2(acc[3][1], xv3, wA.y);
                fma2(acc[3][2], xv3, wB.x); fma2(acc[3][3], xv3, wB.y);
            }
            __syncthreads();   // all reads of buf[ic&1] done before it is refilled
        }

        // ---- epilogue: acc = {y[u0], y[u1]} at (t, og); float2 store, 4-lane full sectors ----
#pragma unroll
        for (int tt = 0; tt < 4; ++tt) {
            const int t = t0 + t_blk * 4 + tt;
#pragma unroll
            for (int oo = 0; oo < 4; ++oo) {
                const int og = oh * O_PER_CTA + o_blk * 4 + oo;
                float2 a = unpack2(acc[tt][oo]);
                float2 r = make_float2(a.x + bz[oo].x, a.y + bz[oo].y);
                *reinterpret_cast<float2*>(
                    yb + ((size_t)og * TLEN + t) * FF + g * UU + u0) = r;
            }
        }
    }
}

extern "C" void kernel_launch(void* const* d_in, const int* in_sizes, int n_in,
                              void* d_out, int out_size) {
    (void)in_sizes; (void)n_in; (void)out_size;
    const float* x    = (const float*)d_in[0];
    const float* w    = (const float*)d_in[1];
    const float* bias = (const float*)d_in[2];
    float*       y    = (float*)d_out;

    cudaFuncSetAttribute(grouped_linear_cf_kernel,
                         cudaFuncAttributeMaxDynamicSharedMemorySize, SMEM_BYTES);

    dim3 grid(GG, BQ, 8);   // 32 groups x 8 batch x (2 o-halves * 4 t-ranges) = 2048 CTAs
    grouped_linear_cf_kernel<<<grid, 512, SMEM_BYTES>>>(x, w, bias, y);
}